// round 16
// baseline (speedup 1.0000x reference)
#include <cuda_runtime.h>
#include <cuda_bf16.h>
#include <cstdint>
#include <cstddef>

#define TT 1024
#define II 64
#define HH 128
#define NCTA 128

typedef unsigned long long u64;

// ---- loop-kernel smem layout (bytes) ----
// weights: [16 slots][512 threads] x 16B ; slot = gate*4 + p (p = 8-k group)
#define OFF_WS  0         // 16*512*16 = 131072
#define OFF_H   131072    // float [2 buf][4 r][128 j] = 4096 B
#define OFF_WEF 135168    // float [128]
#define OFF_BE  135680    // float [4]
#define SMEM_BYTES 135696

// ---- xproj smem layout (floats) ----
#define XROW 260
#define WROW 516
#define XP_SMEM_FLOATS (64 * XROW + 64 * WROW)
#define XP_SMEM_BYTES  (XP_SMEM_FLOATS * 4)   // 198656

// xp scratch: [b][t][g] fp32, bias pre-added (+pad so s+1 prefetch at last step is safe)
__device__ float g_xp[(size_t)512 * TT * 512 + 1024];

__device__ __forceinline__ u64 fma2(u64 a, u64 b, u64 c) {
    u64 d;
    asm("fma.rn.f32x2 %0, %1, %2, %3;" : "=l"(d) : "l"(a), "l"(b), "l"(c));
    return d;
}
__device__ __forceinline__ u64 add2(u64 a, u64 b) {
    u64 d;
    asm("add.rn.f32x2 %0, %1, %2;" : "=l"(d) : "l"(a), "l"(b));
    return d;
}
__device__ __forceinline__ void lds_v2(uint32_t a, u64& v0, u64& v1) {
    asm volatile("ld.shared.v2.u64 {%0,%1}, [%2];" : "=l"(v0), "=l"(v1) : "r"(a));
}
__device__ __forceinline__ void lds_v4_u32(uint32_t a, uint32_t& x, uint32_t& y,
                                           uint32_t& z, uint32_t& w) {
    asm volatile("ld.shared.v4.u32 {%0,%1,%2,%3}, [%4];"
                 : "=r"(x), "=r"(y), "=r"(z), "=r"(w) : "r"(a));
}
__device__ __forceinline__ float2 unpack2(u64 v) {
    float2 r;
    asm("mov.b64 {%0,%1}, %2;" : "=f"(r.x), "=f"(r.y) : "l"(v));
    return r;
}
__device__ __forceinline__ u64 pack2(float lo, float hi) {
    u64 v;
    asm("mov.b64 %0, {%1,%2};" : "=l"(v) : "f"(lo), "f"(hi));
    return v;
}
__device__ __forceinline__ u64 splat2(float v) {
    u64 r;
    asm("mov.b64 %0, {%1,%1};" : "=l"(r) : "f"(v));
    return r;
}
// widen packed bf16 pair (u32) to f32x2 (u64): pure bit ops
__device__ __forceinline__ u64 bf2(uint32_t p) {
    uint32_t lo = p << 16;
    uint32_t hi = p & 0xffff0000u;
    u64 v;
    asm("mov.b64 %0, {%1,%2};" : "=l"(v) : "r"(lo), "r"(hi));
    return v;
}
__device__ __forceinline__ uint32_t pack_bf16(float a, float b) {
    __nv_bfloat162 h = __floats2bfloat162_rn(a, b);   // a -> low half
    uint32_t r;
    asm("mov.b32 %0, %1;" : "=r"(r) : "r"(*reinterpret_cast<uint32_t*>(&h)));
    return r;
}
__device__ __forceinline__ float sigmoid_f(float x) {
    return __fdividef(1.0f, 1.0f + __expf(-x));
}
__device__ __forceinline__ float tanh_f(float x) {
    return __fdividef(2.0f, 1.0f + __expf(-2.0f * x)) - 1.0f;
}

// ================= prologue: xp[b][s][g] = x[b][s][:] . W_ih[g][:] + b_ih[g] + b_hh[g] ======
// Register-tiled SGEMM (R14 version — proven).
__global__ void __launch_bounds__(512, 1)
xproj_kernel(const float* __restrict__ x, const float* __restrict__ W_ih,
             const float* __restrict__ b_ih, const float* __restrict__ b_hh)
{
    extern __shared__ float sm[];
    const int t    = threadIdx.x;
    const int b    = blockIdx.x >> 3;
    const int sblk = ((blockIdx.x >> 1) & 3) * 256;
    const int gh   = (blockIdx.x & 1) * 256;

    float* xT = sm;               // [64][XROW]
    float* wT = sm + 64 * XROW;   // [64][WROW]

    {
        const int sl = t >> 6, k = t & 63;
        #pragma unroll
        for (int r = 0; r < 32; ++r)
            xT[k * XROW + r * 8 + sl] =
                x[((size_t)b * TT + sblk + r * 8 + sl) * II + k];
    }
    {
        const int gl0 = t >> 6, k = t & 63;
        #pragma unroll
        for (int r = 0; r < 32; ++r) {
            int gl = r * 8 + gl0;
            int u = gl >> 3, half = (gl >> 2) & 1, j = gl & 3;
            wT[k * WROW + half * 256 + u * 4 + j] = W_ih[(gh + gl) * II + k];
        }
    }
    __syncthreads();

    const int gg  = t & 31;
    const int sgp = t >> 5;
    const uint32_t sbase = (uint32_t)__cvta_generic_to_shared(sm);
    const uint32_t axb = sbase + (sgp * 8) * 4;
    const uint32_t awb = sbase + 64 * XROW * 4 + gg * 16;

    u64 bp[4];
    {
        const float* bi = b_ih + gh + gg * 8;
        const float* bh = b_hh + gh + gg * 8;
        #pragma unroll
        for (int jq = 0; jq < 4; ++jq)
            bp[jq] = pack2(bi[2 * jq] + bh[2 * jq], bi[2 * jq + 1] + bh[2 * jq + 1]);
    }

    #pragma unroll 1
    for (int p = 0; p < 2; ++p) {
        u64 acc[32];
        #pragma unroll
        for (int q = 0; q < 32; ++q) acc[q] = 0ull;

        uint32_t ax = axb + p * 512;
        uint32_t aw = awb;

        #pragma unroll 4
        for (int k = 0; k < 64; ++k) {
            u64 xa, xb, xc, xd, w0, w1, w2, w3;
            lds_v2(ax, xa, xb);
            lds_v2(ax + 16, xc, xd);
            lds_v2(aw, w0, w1);
            lds_v2(aw + 1024, w2, w3);
            ax += XROW * 4; aw += WROW * 4;

            float2 x01 = unpack2(xa), x23 = unpack2(xb);
            float2 x45 = unpack2(xc), x67 = unpack2(xd);
            u64 s0 = splat2(x01.x), s1 = splat2(x01.y);
            u64 s2 = splat2(x23.x), s3 = splat2(x23.y);
            u64 s4 = splat2(x45.x), s5 = splat2(x45.y);
            u64 s6 = splat2(x67.x), s7 = splat2(x67.y);

            acc[0]  = fma2(w0, s0, acc[0]);   acc[1]  = fma2(w1, s0, acc[1]);
            acc[2]  = fma2(w2, s0, acc[2]);   acc[3]  = fma2(w3, s0, acc[3]);
            acc[4]  = fma2(w0, s1, acc[4]);   acc[5]  = fma2(w1, s1, acc[5]);
            acc[6]  = fma2(w2, s1, acc[6]);   acc[7]  = fma2(w3, s1, acc[7]);
            acc[8]  = fma2(w0, s2, acc[8]);   acc[9]  = fma2(w1, s2, acc[9]);
            acc[10] = fma2(w2, s2, acc[10]);  acc[11] = fma2(w3, s2, acc[11]);
            acc[12] = fma2(w0, s3, acc[12]);  acc[13] = fma2(w1, s3, acc[13]);
            acc[14] = fma2(w2, s3, acc[14]);  acc[15] = fma2(w3, s3, acc[15]);
            acc[16] = fma2(w0, s4, acc[16]);  acc[17] = fma2(w1, s4, acc[17]);
            acc[18] = fma2(w2, s4, acc[18]);  acc[19] = fma2(w3, s4, acc[19]);
            acc[20] = fma2(w0, s5, acc[20]);  acc[21] = fma2(w1, s5, acc[21]);
            acc[22] = fma2(w2, s5, acc[22]);  acc[23] = fma2(w3, s5, acc[23]);
            acc[24] = fma2(w0, s6, acc[24]);  acc[25] = fma2(w1, s6, acc[25]);
            acc[26] = fma2(w2, s6, acc[26]);  acc[27] = fma2(w3, s6, acc[27]);
            acc[28] = fma2(w0, s7, acc[28]);  acc[29] = fma2(w1, s7, acc[29]);
            acc[30] = fma2(w2, s7, acc[30]);  acc[31] = fma2(w3, s7, acc[31]);
        }

        #pragma unroll
        for (int i = 0; i < 8; ++i) {
            size_t srow = (size_t)b * TT + sblk + p * 128 + sgp * 8 + i;
            float* dp = &g_xp[srow * 512 + gh + gg * 8];
            u64 o0 = add2(acc[i * 4 + 0], bp[0]);
            u64 o1 = add2(acc[i * 4 + 1], bp[1]);
            u64 o2 = add2(acc[i * 4 + 2], bp[2]);
            u64 o3 = add2(acc[i * 4 + 3], bp[3]);
            reinterpret_cast<ulonglong2*>(dp)[0] = make_ulonglong2(o0, o1);
            reinterpret_cast<ulonglong2*>(dp)[1] = make_ulonglong2(o2, o3);
        }
    }
}

// ================= sequential LSTM loop: 128 CTAs x 512 threads =================
// thread: j = t>>2 (h column), kq = t&3 (k-quarter). The 4 kq partners of a column
// share a warp (lane bits 0-1) -> shuffle butterfly reduction, ONE barrier per step.
// Thread computes partials for ALL 4 gates x ALL 4 rows over its 32 k (weights deduped
// across rows, h broadcasts deduped across gates). Owns (row kq, col j) c/h state.
__global__ void __launch_bounds__(512, 1)
lstm_loop_kernel(const float* __restrict__ W_hh,
                 const float* __restrict__ W1, const float* __restrict__ b1,
                 const float* __restrict__ W2, const float* __restrict__ b2,
                 float* __restrict__ out)
{
    extern __shared__ char smem[];
    const int t  = threadIdx.x;
    const int j  = t >> 2;
    const int kq = t & 3;
    const int r0 = blockIdx.x * 4;
    const uint32_t sb = (uint32_t)__cvta_generic_to_shared(smem);

    // ---- stage bf16 weights: slot = gate*4 + p, entry [slot][t] = 16B = 8 k pairs ----
    {
        #pragma unroll
        for (int g = 0; g < 4; ++g) {
            const float* wp = W_hh + (size_t)(g * 128 + j) * HH + kq * 32;
            #pragma unroll
            for (int p = 0; p < 4; ++p) {
                uint4 v;
                v.x = pack_bf16(wp[p * 8 + 0], wp[p * 8 + 1]);
                v.y = pack_bf16(wp[p * 8 + 2], wp[p * 8 + 3]);
                v.z = pack_bf16(wp[p * 8 + 4], wp[p * 8 + 5]);
                v.w = pack_bf16(wp[p * 8 + 6], wp[p * 8 + 7]);
                *reinterpret_cast<uint4*>(smem + OFF_WS + ((g * 4 + p) * 512 + t) * 16) = v;
            }
        }
    }

    float* hs   = reinterpret_cast<float*>(smem + OFF_H);     // [2][4][128]
    float* weff = reinterpret_cast<float*>(smem + OFF_WEF);
    float* beff = reinterpret_cast<float*>(smem + OFF_BE);

    // zero both h buffers (1024 floats / 512 threads)
    hs[t] = 0.0f;
    hs[512 + t] = 0.0f;

    if (t < 128) {
        float s = 0.0f;
        for (int m = 0; m < 256; ++m) s += W2[m] * W1[m * HH + t];
        weff[t] = s;
    }
    if (t == 128) {
        float s = b2[0];
        for (int m = 0; m < 256; ++m) s += W2[m] * b1[m];
        beff[0] = s;
    }

    const float* xpp = g_xp + ((size_t)(r0 + kq) * TT) * 512 + j;
    float xv0 = __ldg(xpp);
    float xv1 = __ldg(xpp + 128);
    float xv2 = __ldg(xpp + 256);
    float xv3 = __ldg(xpp + 384);
    float cval = 0.0f;

    const uint32_t aW = sb + OFF_WS + t * 16;        // slot stride = 512*16 = 8192
    const uint32_t aH = sb + OFF_H;

    __syncthreads();

    #pragma unroll 1
    for (int s = 0; s < TT; ++s) {
        // prefetch xp for s+1 (pad covers final step)
        const float* xn = xpp + (size_t)(s + 1) * 512;
        float xn0 = __ldg(xn), xn1 = __ldg(xn + 128), xn2 = __ldg(xn + 256), xn3 = __ldg(xn + 384);

        const uint32_t aHb = aH + (s & 1) * 2048 + kq * 128;

        u64 acc[16];   // acc[g*4 + r]
        #pragma unroll
        for (int i = 0; i < 16; ++i) acc[i] = 0ull;

        #pragma unroll
        for (int p = 0; p < 4; ++p) {
            // 4 gates' weights for this 8-k group (coalesced, conflict-free)
            uint32_t q0x, q0y, q0z, q0w, q1x, q1y, q1z, q1w;
            uint32_t q2x, q2y, q2z, q2w, q3x, q3y, q3z, q3w;
            lds_v4_u32(aW + (0 * 4 + p) * 8192, q0x, q0y, q0z, q0w);
            lds_v4_u32(aW + (1 * 4 + p) * 8192, q1x, q1y, q1z, q1w);
            lds_v4_u32(aW + (2 * 4 + p) * 8192, q2x, q2y, q2z, q2w);
            lds_v4_u32(aW + (3 * 4 + p) * 8192, q3x, q3y, q3z, q3w);
            u64 w00 = bf2(q0x), w01 = bf2(q0y), w02 = bf2(q0z), w03 = bf2(q0w);
            u64 w10 = bf2(q1x), w11 = bf2(q1y), w12 = bf2(q1z), w13 = bf2(q1w);
            u64 w20 = bf2(q2x), w21 = bf2(q2y), w22 = bf2(q2z), w23 = bf2(q2w);
            u64 w30 = bf2(q3x), w31 = bf2(q3y), w32 = bf2(q3z), w33 = bf2(q3w);

            #pragma unroll
            for (int r = 0; r < 4; ++r) {
                u64 h0, h1, h2, h3;
                lds_v2(aHb + r * 512 + p * 32, h0, h1);
                lds_v2(aHb + r * 512 + p * 32 + 16, h2, h3);
                acc[0 * 4 + r] = fma2(w00, h0, acc[0 * 4 + r]);
                acc[0 * 4 + r] = fma2(w01, h1, acc[0 * 4 + r]);
                acc[0 * 4 + r] = fma2(w02, h2, acc[0 * 4 + r]);
                acc[0 * 4 + r] = fma2(w03, h3, acc[0 * 4 + r]);
                acc[1 * 4 + r] = fma2(w10, h0, acc[1 * 4 + r]);
                acc[1 * 4 + r] = fma2(w11, h1, acc[1 * 4 + r]);
                acc[1 * 4 + r] = fma2(w12, h2, acc[1 * 4 + r]);
                acc[1 * 4 + r] = fma2(w13, h3, acc[1 * 4 + r]);
                acc[2 * 4 + r] = fma2(w20, h0, acc[2 * 4 + r]);
                acc[2 * 4 + r] = fma2(w21, h1, acc[2 * 4 + r]);
                acc[2 * 4 + r] = fma2(w22, h2, acc[2 * 4 + r]);
                acc[2 * 4 + r] = fma2(w23, h3, acc[2 * 4 + r]);
                acc[3 * 4 + r] = fma2(w30, h0, acc[3 * 4 + r]);
                acc[3 * 4 + r] = fma2(w31, h1, acc[3 * 4 + r]);
                acc[3 * 4 + r] = fma2(w32, h2, acc[3 * 4 + r]);
                acc[3 * 4 + r] = fma2(w33, h3, acc[3 * 4 + r]);
            }
        }

        // horizontal adds + butterfly reduction over kq (lane bits 0-1)
        float S[16];
        #pragma unroll
        for (int i = 0; i < 16; ++i) {
            float2 f = unpack2(acc[i]);
            S[i] = f.x + f.y;
        }
        #pragma unroll
        for (int i = 0; i < 16; ++i)
            S[i] += __shfl_xor_sync(0xffffffffu, S[i], 1);
        #pragma unroll
        for (int i = 0; i < 16; ++i)
            S[i] += __shfl_xor_sync(0xffffffffu, S[i], 2);

        // select this thread's row (r = kq) per gate
        float G[4];
        #pragma unroll
        for (int g = 0; g < 4; ++g) {
            float a01 = (kq & 1) ? S[g * 4 + 1] : S[g * 4 + 0];
            float a23 = (kq & 1) ? S[g * 4 + 3] : S[g * 4 + 2];
            G[g] = (kq & 2) ? a23 : a01;
        }

        float pi = G[0] + xv0;
        float pf = G[1] + xv1;
        float pg = G[2] + xv2;
        float po = G[3] + xv3;
        float ig = sigmoid_f(pi);
        float fg = sigmoid_f(pf);
        float gv = tanh_f(pg);
        float og = sigmoid_f(po);
        cval = fg * cval + ig * gv;
        hs[((s + 1) & 1) * 512 + kq * 128 + j] = og * tanh_f(cval);

        xv0 = xn0; xv1 = xn1; xv2 = xn2; xv3 = xn3;
        __syncthreads();
    }

    // ---- fused fc1+fc2 epilogue (final h in buffer 0 since TT is even) ----
    if (t < 4) {
        float s = beff[0];
        #pragma unroll 8
        for (int jj = 0; jj < HH; ++jj) s += hs[t * 128 + jj] * weff[jj];
        out[r0 + t] = s;
    }
}

extern "C" void kernel_launch(void* const* d_in, const int* in_sizes, int n_in,
                              void* d_out, int out_size) {
    const float* x    = (const float*)d_in[0];
    const float* W_ih = (const float*)d_in[1];
    const float* W_hh = (const float*)d_in[2];
    const float* b_ih = (const float*)d_in[3];
    const float* b_hh = (const float*)d_in[4];
    const float* W1   = (const float*)d_in[5];
    const float* b1   = (const float*)d_in[6];
    const float* W2   = (const float*)d_in[7];
    const float* b2   = (const float*)d_in[8];
    float* out = (float*)d_out;

    cudaFuncSetAttribute(xproj_kernel,
                         cudaFuncAttributeMaxDynamicSharedMemorySize, XP_SMEM_BYTES);
    cudaFuncSetAttribute(lstm_loop_kernel,
                         cudaFuncAttributeMaxDynamicSharedMemorySize, SMEM_BYTES);

    xproj_kernel<<<4096, 512, XP_SMEM_BYTES>>>(x, W_ih, b_ih, b_hh);
    lstm_loop_kernel<<<NCTA, 512, SMEM_BYTES>>>(W_hh, W1, b1, W2, b2, out);
}